// round 3
// baseline (speedup 1.0000x reference)
#include <cuda_runtime.h>
#include <math.h>

#define MAXN 100000
#define MAXE 1600000
#define MAXG 500
#define LL 8
#define BN_EPS 1e-5f

// ---------------- device scratch ----------------
__device__ float g_h[2][(size_t)MAXN * 64];
__device__ float g_pooled[(size_t)MAXG * LL * 64];
__device__ int g_deg[MAXN + 1];
__device__ int g_off[MAXN + 2];
__device__ int g_pos[MAXN + 1];
__device__ int g_csr[MAXE];
__device__ int g_bsum[1024];

// ---------------- f32x2 helpers ----------------
__device__ __forceinline__ unsigned long long pack2(float a, float b) {
    unsigned long long r;
    asm("mov.b64 %0, {%1, %2};" : "=l"(r) : "f"(a), "f"(b));
    return r;
}
__device__ __forceinline__ void unpack2(unsigned long long v, float& a, float& b) {
    asm("mov.b64 {%0, %1}, %2;" : "=f"(a), "=f"(b) : "l"(v));
}
__device__ __forceinline__ void fma2(unsigned long long& acc, unsigned long long a, unsigned long long b) {
    asm("fma.rn.f32x2 %0, %1, %2, %0;" : "+l"(acc) : "l"(a), "l"(b));
}
__device__ __forceinline__ void red4(float4* p, float4 v) {
    asm volatile("red.global.add.v4.f32 [%0], {%1, %2, %3, %4};"
                 :: "l"(p), "f"(v.x), "f"(v.y), "f"(v.z), "f"(v.w) : "memory");
}

// ============ CSR build ============
__global__ __launch_bounds__(256) void deg_count(const int* __restrict__ ei, int E, int* __restrict__ deg) {
    int e = blockIdx.x * 256 + threadIdx.x;
    if (e >= E) return;
    atomicAdd(&deg[ei[E + e]], 1);
}

__global__ __launch_bounds__(512) void chunk_sum(const int* __restrict__ deg, int n, int* __restrict__ bsum) {
    __shared__ int sh[512];
    int t = threadIdx.x;
    int i = blockIdx.x * 512 + t;
    sh[t] = (i < n) ? deg[i] : 0;
    __syncthreads();
#pragma unroll
    for (int s = 256; s > 0; s >>= 1) {
        if (t < s) sh[t] += sh[t + s];
        __syncthreads();
    }
    if (t == 0) bsum[blockIdx.x] = sh[0];
}

__global__ __launch_bounds__(1024) void scan_bsum(int* __restrict__ bsum, int nb) {
    __shared__ int sh[1024];
    int t = threadIdx.x;
    int v = (t < nb) ? bsum[t] : 0;
    sh[t] = v;
    __syncthreads();
    for (int d = 1; d < 1024; d <<= 1) {
        int add = (t >= d) ? sh[t - d] : 0;
        __syncthreads();
        sh[t] += add;
        __syncthreads();
    }
    if (t < nb) bsum[t] = sh[t] - v;   // exclusive
}

__global__ __launch_bounds__(512) void chunk_scan(const int* __restrict__ deg, int n,
                                                  const int* __restrict__ bsum,
                                                  int* __restrict__ off, int* __restrict__ pos) {
    __shared__ int sh[512];
    int t = threadIdx.x;
    int i = blockIdx.x * 512 + t;
    int v = (i < n) ? deg[i] : 0;
    sh[t] = v;
    __syncthreads();
    for (int d = 1; d < 512; d <<= 1) {
        int add = (t >= d) ? sh[t - d] : 0;
        __syncthreads();
        sh[t] += add;
        __syncthreads();
    }
    if (i < n) {
        int ex = sh[t] - v + bsum[blockIdx.x];
        off[i] = ex;
        pos[i] = ex;
    }
}

__global__ __launch_bounds__(256) void csr_scatter(const int* __restrict__ ei, int E,
                                                   int* __restrict__ pos, int* __restrict__ csr) {
    int e = blockIdx.x * 256 + threadIdx.x;
    if (e >= E) return;
    int src = ei[e];
    int dst = ei[E + e];
    int p = atomicAdd(&pos[dst], 1);
    csr[p] = src;
}

// ============ node MLP helpers ============
__device__ __forceinline__ void load_bn_params(float* prm, int tid,
        const float* b1, const float* g1, const float* be1, const float* m1, const float* v1,
        const float* b2, const float* g2, const float* be2, const float* m2, const float* v2) {
    if (tid < 64) {
        float s1 = g1[tid] * rsqrtf(v1[tid] + BN_EPS);
        prm[tid]       = b1[tid];
        prm[64 + tid]  = s1;
        prm[128 + tid] = fmaf(-m1[tid], s1, be1[tid]);
        float s2 = g2[tid] * rsqrtf(v2[tid] + BN_EPS);
        prm[192 + tid] = b2[tid];
        prm[256 + tid] = s2;
        prm[320 + tid] = fmaf(-m2[tid], s2, be2[tid]);
    }
}

// acc[i][p]: node r*8+i, output pair (c*8+2p, c*8+2p+1)
__device__ __forceinline__ void gemm_tile(const float* __restrict__ Wsh,
                                          const float* __restrict__ zs,
                                          int r, int c, unsigned long long acc[8][4]) {
    const float* zbase = zs + r * 8 * 65;
    const float* wbase = Wsh + c * 8;
#pragma unroll 2
    for (int k = 0; k < 64; ++k) {
        unsigned long long zz[8];
#pragma unroll
        for (int i = 0; i < 8; ++i) {
            float z = zbase[i * 65 + k];
            zz[i] = pack2(z, z);
        }
        ulonglong2 wa = *reinterpret_cast<const ulonglong2*>(wbase + k * 64);
        ulonglong2 wb = *reinterpret_cast<const ulonglong2*>(wbase + k * 64 + 4);
#pragma unroll
        for (int i = 0; i < 8; ++i) {
            fma2(acc[i][0], zz[i], wa.x);
            fma2(acc[i][1], zz[i], wa.y);
            fma2(acc[i][2], zz[i], wb.x);
            fma2(acc[i][3], zz[i], wb.y);
        }
    }
}

__device__ __forceinline__ void epilogue(unsigned long long acc[8][4], const float* prm, int c,
                                         int n0, int r, int N, const int* sh_b,
                                         float* hout, float* pooled, int layer) {
    float4 b2a = *reinterpret_cast<const float4*>(prm + 192 + c * 8);
    float4 b2b = *reinterpret_cast<const float4*>(prm + 192 + c * 8 + 4);
    float4 s2a = *reinterpret_cast<const float4*>(prm + 256 + c * 8);
    float4 s2b = *reinterpret_cast<const float4*>(prm + 256 + c * 8 + 4);
    float4 t2a = *reinterpret_cast<const float4*>(prm + 320 + c * 8);
    float4 t2b = *reinterpret_cast<const float4*>(prm + 320 + c * 8 + 4);
#pragma unroll
    for (int i = 0; i < 8; ++i) {
        int node = r * 8 + i;
        int n = n0 + node;
        if (n >= N) break;
        float f0, f1, f2, f3, f4, f5, f6, f7;
        unpack2(acc[i][0], f0, f1);
        unpack2(acc[i][1], f2, f3);
        unpack2(acc[i][2], f4, f5);
        unpack2(acc[i][3], f6, f7);
        float4 oa, ob;
        oa.x = fmaf(fmaxf(f0 + b2a.x, 0.f), s2a.x, t2a.x);
        oa.y = fmaf(fmaxf(f1 + b2a.y, 0.f), s2a.y, t2a.y);
        oa.z = fmaf(fmaxf(f2 + b2a.z, 0.f), s2a.z, t2a.z);
        oa.w = fmaf(fmaxf(f3 + b2a.w, 0.f), s2a.w, t2a.w);
        ob.x = fmaf(fmaxf(f4 + b2b.x, 0.f), s2b.x, t2b.x);
        ob.y = fmaf(fmaxf(f5 + b2b.y, 0.f), s2b.y, t2b.y);
        ob.z = fmaf(fmaxf(f6 + b2b.z, 0.f), s2b.z, t2b.z);
        ob.w = fmaf(fmaxf(f7 + b2b.w, 0.f), s2b.w, t2b.w);
        float4* op = reinterpret_cast<float4*>(hout) + n * 16 + c * 2;
        op[0] = oa;
        op[1] = ob;
        int g = sh_b[node];
        float4* pp = reinterpret_cast<float4*>(pooled) + (size_t)g * 128 + layer * 16 + c * 2;
        red4(pp, oa);
        red4(pp + 1, ob);
    }
}

__device__ __forceinline__ void mid_bn_store(unsigned long long acc[8][4], const float* prm, int c,
                                             int r, float* zs) {
    float4 b1a = *reinterpret_cast<const float4*>(prm + c * 8);
    float4 b1b = *reinterpret_cast<const float4*>(prm + c * 8 + 4);
    float4 s1a = *reinterpret_cast<const float4*>(prm + 64 + c * 8);
    float4 s1b = *reinterpret_cast<const float4*>(prm + 64 + c * 8 + 4);
    float4 t1a = *reinterpret_cast<const float4*>(prm + 128 + c * 8);
    float4 t1b = *reinterpret_cast<const float4*>(prm + 128 + c * 8 + 4);
#pragma unroll
    for (int i = 0; i < 8; ++i) {
        float* zr = zs + (r * 8 + i) * 65 + c * 8;
        float f0, f1, f2, f3, f4, f5, f6, f7;
        unpack2(acc[i][0], f0, f1);
        unpack2(acc[i][1], f2, f3);
        unpack2(acc[i][2], f4, f5);
        unpack2(acc[i][3], f6, f7);
        zr[0] = fmaf(fmaxf(f0 + b1a.x, 0.f), s1a.x, t1a.x);
        zr[1] = fmaf(fmaxf(f1 + b1a.y, 0.f), s1a.y, t1a.y);
        zr[2] = fmaf(fmaxf(f2 + b1a.z, 0.f), s1a.z, t1a.z);
        zr[3] = fmaf(fmaxf(f3 + b1a.w, 0.f), s1a.w, t1a.w);
        zr[4] = fmaf(fmaxf(f4 + b1b.x, 0.f), s1b.x, t1b.x);
        zr[5] = fmaf(fmaxf(f5 + b1b.y, 0.f), s1b.y, t1b.y);
        zr[6] = fmaf(fmaxf(f6 + b1b.z, 0.f), s1b.z, t1b.z);
        zr[7] = fmaf(fmaxf(f7 + b1b.w, 0.f), s1b.w, t1b.w);
    }
}

// ============ fused gather + MLP kernel (layers 1..7) ============
// shared: W1s[4096] | W2s[4096] | prm[384] | zs[128*65]
#define NODE_SMEM_FLOATS (4096 + 4096 + 384 + 128 * 65)
#define NODE0_SMEM_FLOATS (4096 + 384 + 64 + 128 * 65)

__global__ __launch_bounds__(128) void gin_fused(
        const float* __restrict__ hprev,
        const int* __restrict__ off, const int* __restrict__ csr,
        float* __restrict__ hout, const int* __restrict__ batch,
        float* __restrict__ pooled, int layer, const float* __restrict__ eps,
        const float* __restrict__ W1, const float* __restrict__ b1,
        const float* __restrict__ g1, const float* __restrict__ be1,
        const float* __restrict__ m1, const float* __restrict__ v1,
        const float* __restrict__ W2, const float* __restrict__ b2,
        const float* __restrict__ g2, const float* __restrict__ be2,
        const float* __restrict__ m2, const float* __restrict__ v2, int N) {
    extern __shared__ float sm[];
    float* W1s = sm;
    float* W2s = sm + 4096;
    float* prm = sm + 8192;
    float* zs  = sm + 8576;
    __shared__ int sh_b[128];
    int tid = threadIdx.x;

    float4* w1d = reinterpret_cast<float4*>(W1s);
    float4* w2d = reinterpret_cast<float4*>(W2s);
    const float4* w1g = reinterpret_cast<const float4*>(W1);
    const float4* w2g = reinterpret_cast<const float4*>(W2);
#pragma unroll
    for (int i = tid; i < 1024; i += 128) { w1d[i] = w1g[i]; w2d[i] = w2g[i]; }
    load_bn_params(prm, tid, b1, g1, be1, m1, v1, b2, g2, be2, m2, v2);

    int n0 = blockIdx.x * 128;
    float ev = 1.0f + eps[0];
    if (tid < 128) {
        int n = n0 + tid;
        sh_b[tid] = (n < N) ? batch[n] : 0;
    }

    // ---- fused gather: 16 threads per node, float4 lanes ----
    const float4* h4 = reinterpret_cast<const float4*>(hprev);
    int q = tid & 15;
    int sub = tid >> 4;          // 0..7
#pragma unroll 1
    for (int pass = 0; pass < 16; ++pass) {
        int node = pass * 8 + sub;
        int n = n0 + node;
        float4 acc = make_float4(0.f, 0.f, 0.f, 0.f);
        if (n < N) {
            int b = off[n], e = off[n + 1];
            const float4* hq = h4 + q;
            int i = b;
            for (; i + 4 <= e; i += 4) {
                int i0 = __ldg(&csr[i]);
                int i1 = __ldg(&csr[i + 1]);
                int i2 = __ldg(&csr[i + 2]);
                int i3 = __ldg(&csr[i + 3]);
                float4 v0 = hq[i0 * 16];
                float4 v1 = hq[i1 * 16];
                float4 v2 = hq[i2 * 16];
                float4 v3 = hq[i3 * 16];
                acc.x += (v0.x + v1.x) + (v2.x + v3.x);
                acc.y += (v0.y + v1.y) + (v2.y + v3.y);
                acc.z += (v0.z + v1.z) + (v2.z + v3.z);
                acc.w += (v0.w + v1.w) + (v2.w + v3.w);
            }
            for (; i < e; ++i) {
                float4 v = hq[__ldg(&csr[i]) * 16];
                acc.x += v.x; acc.y += v.y; acc.z += v.z; acc.w += v.w;
            }
            float4 hv = h4[n * 16 + q];
            acc.x = fmaf(ev, hv.x, acc.x);
            acc.y = fmaf(ev, hv.y, acc.y);
            acc.z = fmaf(ev, hv.z, acc.z);
            acc.w = fmaf(ev, hv.w, acc.w);
        }
        float* zr = zs + node * 65 + q * 4;
        zr[0] = acc.x; zr[1] = acc.y; zr[2] = acc.z; zr[3] = acc.w;
    }
    __syncthreads();

    int r = tid >> 3, c = tid & 7;
    unsigned long long acc[8][4];
#pragma unroll
    for (int i = 0; i < 8; ++i)
#pragma unroll
        for (int p = 0; p < 4; ++p) acc[i][p] = 0ull;

    gemm_tile(W1s, zs, r, c, acc);
    __syncthreads();
    mid_bn_store(acc, prm, c, r, zs);
#pragma unroll
    for (int i = 0; i < 8; ++i)
#pragma unroll
        for (int p = 0; p < 4; ++p) acc[i][p] = 0ull;
    __syncthreads();
    gemm_tile(W2s, zs, r, c, acc);
    epilogue(acc, prm, c, n0, r, N, sh_b, hout, pooled, layer);
}

// ============ layer 0 (scalar input, fused scalar gather) ============
__global__ __launch_bounds__(128) void gin_node0(
        const float* __restrict__ x,
        const int* __restrict__ off, const int* __restrict__ csr,
        float* __restrict__ hout, const int* __restrict__ batch,
        float* __restrict__ pooled, const float* __restrict__ eps,
        const float* __restrict__ W1f, const float* __restrict__ b1,
        const float* __restrict__ g1, const float* __restrict__ be1,
        const float* __restrict__ m1, const float* __restrict__ v1,
        const float* __restrict__ W2, const float* __restrict__ b2,
        const float* __restrict__ g2, const float* __restrict__ be2,
        const float* __restrict__ m2, const float* __restrict__ v2, int N) {
    extern __shared__ float sm[];
    float* W2s = sm;
    float* prm = sm + 4096;
    float* w1f = sm + 4480;
    float* zs  = sm + 4544;
    __shared__ int sh_b[128];
    int tid = threadIdx.x;

    float4* w2d = reinterpret_cast<float4*>(W2s);
    const float4* w2g = reinterpret_cast<const float4*>(W2);
#pragma unroll
    for (int i = tid; i < 1024; i += 128) w2d[i] = w2g[i];
    if (tid < 64) w1f[tid] = W1f[tid];
    load_bn_params(prm, tid, b1, g1, be1, m1, v1, b2, g2, be2, m2, v2);
    __syncthreads();

    int n0 = blockIdx.x * 128;
    int n = n0 + tid;
    float* zrow = zs + tid * 65;
    if (n < N) {
        sh_b[tid] = batch[n];
        int b = off[n], e = off[n + 1];
        float s = 0.f;
        int i = b;
        for (; i + 4 <= e; i += 4) {
            float v0 = x[__ldg(&csr[i])];
            float v1 = x[__ldg(&csr[i + 1])];
            float v2 = x[__ldg(&csr[i + 2])];
            float v3 = x[__ldg(&csr[i + 3])];
            s += (v0 + v1) + (v2 + v3);
        }
        for (; i < e; ++i) s += x[__ldg(&csr[i])];
        float ev = 1.0f + eps[0];
        float z = fmaf(ev, x[n], s);
#pragma unroll
        for (int j = 0; j < 64; ++j) {
            float y = fmaxf(fmaf(z, w1f[j], prm[j]), 0.f);
            zrow[j] = fmaf(y, prm[64 + j], prm[128 + j]);
        }
    } else {
        sh_b[tid] = 0;
#pragma unroll
        for (int j = 0; j < 64; ++j) zrow[j] = 0.f;
    }
    __syncthreads();

    int r = tid >> 3, c = tid & 7;
    unsigned long long acc[8][4];
#pragma unroll
    for (int i = 0; i < 8; ++i)
#pragma unroll
        for (int p = 0; p < 4; ++p) acc[i][p] = 0ull;
    gemm_tile(W2s, zs, r, c, acc);
    epilogue(acc, prm, c, n0, r, N, sh_b, hout, pooled, 0);
}

// ---------------- classifier head ----------------
__device__ __forceinline__ int lbound(const int* __restrict__ a, int n, int v) {
    int lo = 0, hi = n;
    while (lo < hi) {
        int mid = (lo + hi) >> 1;
        if (a[mid] < v) lo = mid + 1; else hi = mid;
    }
    return lo;
}

__global__ __launch_bounds__(64) void classify_kernel(
        const float* __restrict__ pooled, const int* __restrict__ batch, int N,
        const float* __restrict__ lw1, const float* __restrict__ lb1,
        const float* __restrict__ lw2, const float* __restrict__ lb2,
        float* __restrict__ out) {
    __shared__ float ps[512];
    __shared__ float hid[64];
    __shared__ float lg[3];
    __shared__ float inv;
    int g = blockIdx.x;
    int tid = threadIdx.x;
    if (tid == 0) {
        int a = lbound(batch, N, g);
        int b = lbound(batch, N, g + 1);
        int c = b - a;
        inv = 1.0f / (float)(c > 1 ? c : 1);
    }
    __syncthreads();
    for (int k = tid; k < 512; k += 64) ps[k] = pooled[(size_t)g * 512 + k] * inv;
    __syncthreads();
    float acc = lb1[tid];
#pragma unroll 8
    for (int k = 0; k < 512; ++k) acc = fmaf(ps[k], lw1[k * 64 + tid], acc);
    hid[tid] = fmaxf(acc, 0.f);
    __syncthreads();
    if (tid < 3) {
        float s = lb2[tid];
#pragma unroll
        for (int j = 0; j < 64; ++j) s = fmaf(hid[j], lw2[j * 3 + tid], s);
        lg[tid] = s;
    }
    __syncthreads();
    if (tid == 0) {
        float m = fmaxf(lg[0], fmaxf(lg[1], lg[2]));
        float e = expf(lg[0] - m) + expf(lg[1] - m) + expf(lg[2] - m);
        float lse = m + logf(e);
        out[g * 3 + 0] = lg[0] - lse;
        out[g * 3 + 1] = lg[1] - lse;
        out[g * 3 + 2] = lg[2] - lse;
    }
}

// ---------------- launcher ----------------
extern "C" void kernel_launch(void* const* d_in, const int* in_sizes, int n_in,
                              void* d_out, int out_size) {
    const float* x     = (const float*)d_in[0];
    const int*   ei    = (const int*)d_in[1];
    const int*   batch = (const int*)d_in[2];
    int bi = (in_sizes[3] == 1) ? 4 : 3;
    const float* eps  = (const float*)d_in[bi + 0];
    const float* W1f  = (const float*)d_in[bi + 1];
    const float* W1r  = (const float*)d_in[bi + 2];
    const float* b1   = (const float*)d_in[bi + 3];
    const float* g1   = (const float*)d_in[bi + 4];
    const float* be1  = (const float*)d_in[bi + 5];
    const float* m1   = (const float*)d_in[bi + 6];
    const float* v1   = (const float*)d_in[bi + 7];
    const float* W2   = (const float*)d_in[bi + 8];
    const float* b2   = (const float*)d_in[bi + 9];
    const float* g2   = (const float*)d_in[bi + 10];
    const float* be2  = (const float*)d_in[bi + 11];
    const float* m2   = (const float*)d_in[bi + 12];
    const float* v2   = (const float*)d_in[bi + 13];
    const float* lw1  = (const float*)d_in[bi + 14];
    const float* lb1  = (const float*)d_in[bi + 15];
    const float* lw2  = (const float*)d_in[bi + 16];
    const float* lb2  = (const float*)d_in[bi + 17];

    int N = in_sizes[0];
    int E = in_sizes[1] / 2;
    int G = out_size / 3;
    if (N > MAXN) N = MAXN;
    if (E > MAXE) E = MAXE;
    if (G > MAXG) G = MAXG;

    float *h0, *h1, *pooled;
    int *deg, *off, *pos, *csr, *bsum;
    cudaGetSymbolAddress((void**)&h0, g_h);
    h1 = h0 + (size_t)MAXN * 64;
    cudaGetSymbolAddress((void**)&pooled, g_pooled);
    cudaGetSymbolAddress((void**)&deg, g_deg);
    cudaGetSymbolAddress((void**)&off, g_off);
    cudaGetSymbolAddress((void**)&pos, g_pos);
    cudaGetSymbolAddress((void**)&csr, g_csr);
    cudaGetSymbolAddress((void**)&bsum, g_bsum);

    cudaFuncSetAttribute(gin_fused, cudaFuncAttributeMaxDynamicSharedMemorySize,
                         NODE_SMEM_FLOATS * 4);
    cudaFuncSetAttribute(gin_node0, cudaFuncAttributeMaxDynamicSharedMemorySize,
                         NODE0_SMEM_FLOATS * 4);

    int nodeGrid = (N + 127) / 128;
    int edgeGrid = (E + 255) / 256;
    int nScan = N + 1;
    int nb = (nScan + 511) / 512;

    // ----- CSR build -----
    cudaMemsetAsync(deg, 0, (size_t)nScan * sizeof(int));
    cudaMemsetAsync(pooled, 0, (size_t)G * 512 * sizeof(float));
    deg_count<<<edgeGrid, 256>>>(ei, E, deg);
    chunk_sum<<<nb, 512>>>(deg, nScan, bsum);
    scan_bsum<<<1, 1024>>>(bsum, nb);
    chunk_scan<<<nb, 512>>>(deg, nScan, bsum, off, pos);
    csr_scatter<<<edgeGrid, 256>>>(ei, E, pos, csr);

    // ----- layer 0 (scalar input, fused) -----
    gin_node0<<<nodeGrid, 128, NODE0_SMEM_FLOATS * 4>>>(
        x, off, csr, h0, batch, pooled, eps, W1f,
        b1, g1, be1, m1, v1,
        W2, b2, g2, be2, m2, v2, N);

    // ----- layers 1..7 (fused gather + MLP) -----
    for (int i = 1; i < LL; ++i) {
        const float* hprev = (i & 1) ? h0 : h1;
        float* hout = (i & 1) ? h1 : h0;
        gin_fused<<<nodeGrid, 128, NODE_SMEM_FLOATS * 4>>>(
            hprev, off, csr, hout, batch, pooled, i, eps + i,
            W1r + (size_t)(i - 1) * 4096, b1 + i * 64,
            g1 + i * 64, be1 + i * 64, m1 + i * 64, v1 + i * 64,
            W2 + (size_t)i * 4096, b2 + i * 64,
            g2 + i * 64, be2 + i * 64, m2 + i * 64, v2 + i * 64, N);
    }

    // ----- head -----
    classify_kernel<<<G, 64>>>(pooled, batch, N, lw1, lb1, lw2, lb2, (float*)d_out);
}

// round 5
// speedup vs baseline: 1.5145x; 1.5145x over previous
#include <cuda_runtime.h>
#include <cuda_bf16.h>
#include <math.h>

#define MAXN 100000
#define MAXE 1600000
#define MAXG 500
#define LL 8
#define BN_EPS 1e-5f

// ---------------- device scratch ----------------
__device__ __nv_bfloat162 g_hh[2][(size_t)MAXN * 32];  // bf16 node features (128B rows)
__device__ float g_z[(size_t)MAXN * 64];                // z = (1+eps)*h + agg (fp32)
__device__ float g_pooled[(size_t)MAXG * LL * 64];
__device__ int g_deg[MAXN + 1];
__device__ int g_off[MAXN + 2];
__device__ int g_pos[MAXN + 1];
__device__ int g_csr[MAXE];
__device__ int g_bsum[1024];

// ---------------- f32x2 helpers ----------------
__device__ __forceinline__ unsigned long long pack2(float a, float b) {
    unsigned long long r;
    asm("mov.b64 %0, {%1, %2};" : "=l"(r) : "f"(a), "f"(b));
    return r;
}
__device__ __forceinline__ void unpack2(unsigned long long v, float& a, float& b) {
    asm("mov.b64 {%0, %1}, %2;" : "=f"(a), "=f"(b) : "l"(v));
}
__device__ __forceinline__ void fma2(unsigned long long& acc, unsigned long long a, unsigned long long b) {
    asm("fma.rn.f32x2 %0, %1, %2, %0;" : "+l"(acc) : "l"(a), "l"(b));
}
__device__ __forceinline__ void red4(float4* p, float4 v) {
    asm volatile("red.global.add.v4.f32 [%0], {%1, %2, %3, %4};"
                 :: "l"(p), "f"(v.x), "f"(v.y), "f"(v.z), "f"(v.w) : "memory");
}

// ============ CSR build ============
__global__ __launch_bounds__(256) void deg_count(const int* __restrict__ ei, int E, int* __restrict__ deg) {
    int e = blockIdx.x * 256 + threadIdx.x;
    if (e >= E) return;
    atomicAdd(&deg[ei[E + e]], 1);
}

__global__ __launch_bounds__(512) void chunk_sum(const int* __restrict__ deg, int n, int* __restrict__ bsum) {
    __shared__ int sh[512];
    int t = threadIdx.x;
    int i = blockIdx.x * 512 + t;
    sh[t] = (i < n) ? deg[i] : 0;
    __syncthreads();
#pragma unroll
    for (int s = 256; s > 0; s >>= 1) {
        if (t < s) sh[t] += sh[t + s];
        __syncthreads();
    }
    if (t == 0) bsum[blockIdx.x] = sh[0];
}

__global__ __launch_bounds__(1024) void scan_bsum(int* __restrict__ bsum, int nb) {
    __shared__ int sh[1024];
    int t = threadIdx.x;
    int v = (t < nb) ? bsum[t] : 0;
    sh[t] = v;
    __syncthreads();
    for (int d = 1; d < 1024; d <<= 1) {
        int add = (t >= d) ? sh[t - d] : 0;
        __syncthreads();
        sh[t] += add;
        __syncthreads();
    }
    if (t < nb) bsum[t] = sh[t] - v;   // exclusive
}

__global__ __launch_bounds__(512) void chunk_scan(const int* __restrict__ deg, int n,
                                                  const int* __restrict__ bsum,
                                                  int* __restrict__ off, int* __restrict__ pos) {
    __shared__ int sh[512];
    int t = threadIdx.x;
    int i = blockIdx.x * 512 + t;
    int v = (i < n) ? deg[i] : 0;
    sh[t] = v;
    __syncthreads();
    for (int d = 1; d < 512; d <<= 1) {
        int add = (t >= d) ? sh[t - d] : 0;
        __syncthreads();
        sh[t] += add;
        __syncthreads();
    }
    if (i < n) {
        int ex = sh[t] - v + bsum[blockIdx.x];
        off[i] = ex;
        pos[i] = ex;
    }
}

__global__ __launch_bounds__(256) void csr_scatter(const int* __restrict__ ei, int E,
                                                   int* __restrict__ pos, int* __restrict__ csr) {
    int e = blockIdx.x * 256 + threadIdx.x;
    if (e >= E) return;
    int src = ei[e];
    int dst = ei[E + e];
    int p = atomicAdd(&pos[dst], 1);
    csr[p] = src;
}

// ============ CSR aggregation (bf16 rows -> fp32 z) ============
__device__ __forceinline__ void addrow(float4 v, float* acc) {
    const __nv_bfloat162* h = reinterpret_cast<const __nv_bfloat162*>(&v);
#pragma unroll
    for (int j = 0; j < 4; ++j) {
        float2 f = __bfloat1622float2(h[j]);
        acc[2 * j]     += f.x;
        acc[2 * j + 1] += f.y;
    }
}

// 8 threads per node, each thread covers 8 contiguous features (16B).
__global__ __launch_bounds__(256) void csr_agg_h(const int* __restrict__ off, const int* __restrict__ csr,
                                                 const __nv_bfloat162* __restrict__ hh, float* __restrict__ z,
                                                 const float* __restrict__ eps, int N) {
    int t = blockIdx.x * 256 + threadIdx.x;
    int n = t >> 3;
    if (n >= N) return;
    int q = t & 7;
    const float4* hq = reinterpret_cast<const float4*>(hh) + q;
    float acc[8];
#pragma unroll
    for (int j = 0; j < 8; ++j) acc[j] = 0.f;
    int b = off[n], e = off[n + 1];
    int i = b;
    for (; i + 4 <= e; i += 4) {
        int i0 = __ldg(&csr[i]);
        int i1 = __ldg(&csr[i + 1]);
        int i2 = __ldg(&csr[i + 2]);
        int i3 = __ldg(&csr[i + 3]);
        float4 v0 = hq[i0 * 8];
        float4 v1 = hq[i1 * 8];
        float4 v2 = hq[i2 * 8];
        float4 v3 = hq[i3 * 8];
        addrow(v0, acc);
        addrow(v1, acc);
        addrow(v2, acc);
        addrow(v3, acc);
    }
    for (; i < e; ++i) addrow(hq[__ldg(&csr[i]) * 8], acc);

    // self term
    float ev = 1.0f + eps[0];
    float4 sv = hq[n * 8];
    const __nv_bfloat162* sh2 = reinterpret_cast<const __nv_bfloat162*>(&sv);
    float4 o0, o1;
    {
        float2 f0 = __bfloat1622float2(sh2[0]);
        float2 f1 = __bfloat1622float2(sh2[1]);
        float2 f2 = __bfloat1622float2(sh2[2]);
        float2 f3 = __bfloat1622float2(sh2[3]);
        o0.x = fmaf(ev, f0.x, acc[0]);
        o0.y = fmaf(ev, f0.y, acc[1]);
        o0.z = fmaf(ev, f1.x, acc[2]);
        o0.w = fmaf(ev, f1.y, acc[3]);
        o1.x = fmaf(ev, f2.x, acc[4]);
        o1.y = fmaf(ev, f2.y, acc[5]);
        o1.z = fmaf(ev, f3.x, acc[6]);
        o1.w = fmaf(ev, f3.y, acc[7]);
    }
    float4* zp = reinterpret_cast<float4*>(z + (size_t)n * 64 + q * 8);
    zp[0] = o0;
    zp[1] = o1;
}

// scalar features (layer 0)
__global__ __launch_bounds__(256) void csr_agg1(const int* __restrict__ off, const int* __restrict__ csr,
                                                const float* __restrict__ x, float* __restrict__ agg, int N) {
    int n = blockIdx.x * 256 + threadIdx.x;
    if (n >= N) return;
    int b = off[n], e = off[n + 1];
    float s = 0.f;
    int i = b;
    for (; i + 4 <= e; i += 4) {
        float v0 = x[__ldg(&csr[i])];
        float v1 = x[__ldg(&csr[i + 1])];
        float v2 = x[__ldg(&csr[i + 2])];
        float v3 = x[__ldg(&csr[i + 3])];
        s += (v0 + v1) + (v2 + v3);
    }
    for (; i < e; ++i) s += x[__ldg(&csr[i])];
    agg[n] = s;
}

// ============ node MLP (register-tiled 8x8 GEMM) ============
#define NODE_SMEM_FLOATS (4096 + 4096 + 384 + 128 * 65)
#define NODE0_SMEM_FLOATS (4096 + 384 + 64 + 128 * 65)

__device__ __forceinline__ void load_bn_params(float* prm, int tid,
        const float* b1, const float* g1, const float* be1, const float* m1, const float* v1,
        const float* b2, const float* g2, const float* be2, const float* m2, const float* v2) {
    if (tid < 64) {
        float s1 = g1[tid] * rsqrtf(v1[tid] + BN_EPS);
        prm[tid]       = b1[tid];
        prm[64 + tid]  = s1;
        prm[128 + tid] = fmaf(-m1[tid], s1, be1[tid]);
        float s2 = g2[tid] * rsqrtf(v2[tid] + BN_EPS);
        prm[192 + tid] = b2[tid];
        prm[256 + tid] = s2;
        prm[320 + tid] = fmaf(-m2[tid], s2, be2[tid]);
    }
}

__device__ __forceinline__ void gemm_tile(const float* __restrict__ Wsh,
                                          const float* __restrict__ zs,
                                          int r, int c, unsigned long long acc[8][4]) {
    const float* zbase = zs + r * 8 * 65;
    const float* wbase = Wsh + c * 8;
#pragma unroll 2
    for (int k = 0; k < 64; ++k) {
        unsigned long long zz[8];
#pragma unroll
        for (int i = 0; i < 8; ++i) {
            float z = zbase[i * 65 + k];
            zz[i] = pack2(z, z);
        }
        ulonglong2 wa = *reinterpret_cast<const ulonglong2*>(wbase + k * 64);
        ulonglong2 wb = *reinterpret_cast<const ulonglong2*>(wbase + k * 64 + 4);
#pragma unroll
        for (int i = 0; i < 8; ++i) {
            fma2(acc[i][0], zz[i], wa.x);
            fma2(acc[i][1], zz[i], wa.y);
            fma2(acc[i][2], zz[i], wb.x);
            fma2(acc[i][3], zz[i], wb.y);
        }
    }
}

// BN2 + write bf16 hout + RED pooled (pooled uses exact fp32 values)
__device__ __forceinline__ void epilogue(unsigned long long acc[8][4], const float* prm, int c,
                                         int n0, int r, int N, const int* sh_b,
                                         __nv_bfloat162* houth, float* pooled, int layer) {
    float4 b2a = *reinterpret_cast<const float4*>(prm + 192 + c * 8);
    float4 b2b = *reinterpret_cast<const float4*>(prm + 192 + c * 8 + 4);
    float4 s2a = *reinterpret_cast<const float4*>(prm + 256 + c * 8);
    float4 s2b = *reinterpret_cast<const float4*>(prm + 256 + c * 8 + 4);
    float4 t2a = *reinterpret_cast<const float4*>(prm + 320 + c * 8);
    float4 t2b = *reinterpret_cast<const float4*>(prm + 320 + c * 8 + 4);
#pragma unroll
    for (int i = 0; i < 8; ++i) {
        int node = r * 8 + i;
        int n = n0 + node;
        if (n >= N) break;
        float f0, f1, f2, f3, f4, f5, f6, f7;
        unpack2(acc[i][0], f0, f1);
        unpack2(acc[i][1], f2, f3);
        unpack2(acc[i][2], f4, f5);
        unpack2(acc[i][3], f6, f7);
        float4 oa, ob;
        oa.x = fmaf(fmaxf(f0 + b2a.x, 0.f), s2a.x, t2a.x);
        oa.y = fmaf(fmaxf(f1 + b2a.y, 0.f), s2a.y, t2a.y);
        oa.z = fmaf(fmaxf(f2 + b2a.z, 0.f), s2a.z, t2a.z);
        oa.w = fmaf(fmaxf(f3 + b2a.w, 0.f), s2a.w, t2a.w);
        ob.x = fmaf(fmaxf(f4 + b2b.x, 0.f), s2b.x, t2b.x);
        ob.y = fmaf(fmaxf(f5 + b2b.y, 0.f), s2b.y, t2b.y);
        ob.z = fmaf(fmaxf(f6 + b2b.z, 0.f), s2b.z, t2b.z);
        ob.w = fmaf(fmaxf(f7 + b2b.w, 0.f), s2b.w, t2b.w);
        __nv_bfloat162 p0 = __floats2bfloat162_rn(oa.x, oa.y);
        __nv_bfloat162 p1 = __floats2bfloat162_rn(oa.z, oa.w);
        __nv_bfloat162 p2 = __floats2bfloat162_rn(ob.x, ob.y);
        __nv_bfloat162 p3 = __floats2bfloat162_rn(ob.z, ob.w);
        uint4 u;
        u.x = *reinterpret_cast<unsigned*>(&p0);
        u.y = *reinterpret_cast<unsigned*>(&p1);
        u.z = *reinterpret_cast<unsigned*>(&p2);
        u.w = *reinterpret_cast<unsigned*>(&p3);
        reinterpret_cast<uint4*>(houth)[n * 8 + c] = u;
        int g = sh_b[node];
        float4* pp = reinterpret_cast<float4*>(pooled) + (size_t)g * 128 + layer * 16 + c * 2;
        red4(pp, oa);
        red4(pp + 1, ob);
    }
}

__device__ __forceinline__ void mid_bn_store(unsigned long long acc[8][4], const float* prm, int c,
                                             int r, float* zs) {
    float4 b1a = *reinterpret_cast<const float4*>(prm + c * 8);
    float4 b1b = *reinterpret_cast<const float4*>(prm + c * 8 + 4);
    float4 s1a = *reinterpret_cast<const float4*>(prm + 64 + c * 8);
    float4 s1b = *reinterpret_cast<const float4*>(prm + 64 + c * 8 + 4);
    float4 t1a = *reinterpret_cast<const float4*>(prm + 128 + c * 8);
    float4 t1b = *reinterpret_cast<const float4*>(prm + 128 + c * 8 + 4);
#pragma unroll
    for (int i = 0; i < 8; ++i) {
        float* zr = zs + (r * 8 + i) * 65 + c * 8;
        float f0, f1, f2, f3, f4, f5, f6, f7;
        unpack2(acc[i][0], f0, f1);
        unpack2(acc[i][1], f2, f3);
        unpack2(acc[i][2], f4, f5);
        unpack2(acc[i][3], f6, f7);
        zr[0] = fmaf(fmaxf(f0 + b1a.x, 0.f), s1a.x, t1a.x);
        zr[1] = fmaf(fmaxf(f1 + b1a.y, 0.f), s1a.y, t1a.y);
        zr[2] = fmaf(fmaxf(f2 + b1a.z, 0.f), s1a.z, t1a.z);
        zr[3] = fmaf(fmaxf(f3 + b1a.w, 0.f), s1a.w, t1a.w);
        zr[4] = fmaf(fmaxf(f4 + b1b.x, 0.f), s1b.x, t1b.x);
        zr[5] = fmaf(fmaxf(f5 + b1b.y, 0.f), s1b.y, t1b.y);
        zr[6] = fmaf(fmaxf(f6 + b1b.z, 0.f), s1b.z, t1b.z);
        zr[7] = fmaf(fmaxf(f7 + b1b.w, 0.f), s1b.w, t1b.w);
    }
}

__global__ __launch_bounds__(128) void gin_node(
        const float* __restrict__ zsrc,
        __nv_bfloat162* __restrict__ houth, const int* __restrict__ batch,
        float* __restrict__ pooled, int layer,
        const float* __restrict__ W1, const float* __restrict__ b1,
        const float* __restrict__ g1, const float* __restrict__ be1,
        const float* __restrict__ m1, const float* __restrict__ v1,
        const float* __restrict__ W2, const float* __restrict__ b2,
        const float* __restrict__ g2, const float* __restrict__ be2,
        const float* __restrict__ m2, const float* __restrict__ v2, int N) {
    extern __shared__ float sm[];
    float* W1s = sm;
    float* W2s = sm + 4096;
    float* prm = sm + 8192;
    float* zs  = sm + 8576;
    __shared__ int sh_b[128];
    int tid = threadIdx.x;

    float4* w1d = reinterpret_cast<float4*>(W1s);
    float4* w2d = reinterpret_cast<float4*>(W2s);
    const float4* w1g = reinterpret_cast<const float4*>(W1);
    const float4* w2g = reinterpret_cast<const float4*>(W2);
#pragma unroll
    for (int i = tid; i < 1024; i += 128) { w1d[i] = w1g[i]; w2d[i] = w2g[i]; }
    load_bn_params(prm, tid, b1, g1, be1, m1, v1, b2, g2, be2, m2, v2);

    int n0 = blockIdx.x * 128;
    int n = n0 + tid;
    float* zr = zs + tid * 65;
    if (n < N) {
        sh_b[tid] = batch[n];
        const float4* zp = reinterpret_cast<const float4*>(zsrc) + n * 16;
#pragma unroll
        for (int q = 0; q < 16; ++q) {
            float4 v = zp[q];
            zr[4 * q + 0] = v.x;
            zr[4 * q + 1] = v.y;
            zr[4 * q + 2] = v.z;
            zr[4 * q + 3] = v.w;
        }
    } else {
        sh_b[tid] = 0;
#pragma unroll
        for (int q = 0; q < 64; ++q) zr[q] = 0.f;
    }
    __syncthreads();

    int r = tid >> 3, c = tid & 7;
    unsigned long long acc[8][4];
#pragma unroll
    for (int i = 0; i < 8; ++i)
#pragma unroll
        for (int p = 0; p < 4; ++p) acc[i][p] = 0ull;

    gemm_tile(W1s, zs, r, c, acc);
    __syncthreads();
    mid_bn_store(acc, prm, c, r, zs);
#pragma unroll
    for (int i = 0; i < 8; ++i)
#pragma unroll
        for (int p = 0; p < 4; ++p) acc[i][p] = 0ull;
    __syncthreads();
    gemm_tile(W2s, zs, r, c, acc);
    epilogue(acc, prm, c, n0, r, N, sh_b, houth, pooled, layer);
}

__global__ __launch_bounds__(128) void gin_node0(
        const float* __restrict__ x, const float* __restrict__ agg,
        __nv_bfloat162* __restrict__ houth, const int* __restrict__ batch,
        float* __restrict__ pooled, const float* __restrict__ eps,
        const float* __restrict__ W1f, const float* __restrict__ b1,
        const float* __restrict__ g1, const float* __restrict__ be1,
        const float* __restrict__ m1, const float* __restrict__ v1,
        const float* __restrict__ W2, const float* __restrict__ b2,
        const float* __restrict__ g2, const float* __restrict__ be2,
        const float* __restrict__ m2, const float* __restrict__ v2, int N) {
    extern __shared__ float sm[];
    float* W2s = sm;
    float* prm = sm + 4096;
    float* w1f = sm + 4480;
    float* zs  = sm + 4544;
    __shared__ int sh_b[128];
    int tid = threadIdx.x;

    float4* w2d = reinterpret_cast<float4*>(W2s);
    const float4* w2g = reinterpret_cast<const float4*>(W2);
#pragma unroll
    for (int i = tid; i < 1024; i += 128) w2d[i] = w2g[i];
    if (tid < 64) w1f[tid] = W1f[tid];
    load_bn_params(prm, tid, b1, g1, be1, m1, v1, b2, g2, be2, m2, v2);
    __syncthreads();

    int n0 = blockIdx.x * 128;
    int n = n0 + tid;
    float* zrow = zs + tid * 65;
    if (n < N) {
        sh_b[tid] = batch[n];
        float ev = 1.0f + eps[0];
        float z = fmaf(ev, x[n], agg[n]);
#pragma unroll
        for (int j = 0; j < 64; ++j) {
            float y = fmaxf(fmaf(z, w1f[j], prm[j]), 0.f);
            zrow[j] = fmaf(y, prm[64 + j], prm[128 + j]);
        }
    } else {
        sh_b[tid] = 0;
#pragma unroll
        for (int j = 0; j < 64; ++j) zrow[j] = 0.f;
    }
    __syncthreads();

    int r = tid >> 3, c = tid & 7;
    unsigned long long acc[8][4];
#pragma unroll
    for (int i = 0; i < 8; ++i)
#pragma unroll
        for (int p = 0; p < 4; ++p) acc[i][p] = 0ull;
    gemm_tile(W2s, zs, r, c, acc);
    epilogue(acc, prm, c, n0, r, N, sh_b, houth, pooled, 0);
}

// ---------------- classifier head ----------------
__device__ __forceinline__ int lbound(const int* __restrict__ a, int n, int v) {
    int lo = 0, hi = n;
    while (lo < hi) {
        int mid = (lo + hi) >> 1;
        if (a[mid] < v) lo = mid + 1; else hi = mid;
    }
    return lo;
}

__global__ __launch_bounds__(64) void classify_kernel(
        const float* __restrict__ pooled, const int* __restrict__ batch, int N,
        const float* __restrict__ lw1, const float* __restrict__ lb1,
        const float* __restrict__ lw2, const float* __restrict__ lb2,
        float* __restrict__ out) {
    __shared__ float ps[512];
    __shared__ float hid[64];
    __shared__ float lg[3];
    __shared__ float inv;
    int g = blockIdx.x;
    int tid = threadIdx.x;
    if (tid == 0) {
        int a = lbound(batch, N, g);
        int b = lbound(batch, N, g + 1);
        int c = b - a;
        inv = 1.0f / (float)(c > 1 ? c : 1);
    }
    __syncthreads();
    for (int k = tid; k < 512; k += 64) ps[k] = pooled[(size_t)g * 512 + k] * inv;
    __syncthreads();
    float acc = lb1[tid];
#pragma unroll 8
    for (int k = 0; k < 512; ++k) acc = fmaf(ps[k], lw1[k * 64 + tid], acc);
    hid[tid] = fmaxf(acc, 0.f);
    __syncthreads();
    if (tid < 3) {
        float s = lb2[tid];
#pragma unroll
        for (int j = 0; j < 64; ++j) s = fmaf(hid[j], lw2[j * 3 + tid], s);
        lg[tid] = s;
    }
    __syncthreads();
    if (tid == 0) {
        float m = fmaxf(lg[0], fmaxf(lg[1], lg[2]));
        float e = expf(lg[0] - m) + expf(lg[1] - m) + expf(lg[2] - m);
        float lse = m + logf(e);
        out[g * 3 + 0] = lg[0] - lse;
        out[g * 3 + 1] = lg[1] - lse;
        out[g * 3 + 2] = lg[2] - lse;
    }
}

// ---------------- launcher ----------------
extern "C" void kernel_launch(void* const* d_in, const int* in_sizes, int n_in,
                              void* d_out, int out_size) {
    const float* x     = (const float*)d_in[0];
    const int*   ei    = (const int*)d_in[1];
    const int*   batch = (const int*)d_in[2];
    int bi = (in_sizes[3] == 1) ? 4 : 3;
    const float* eps  = (const float*)d_in[bi + 0];
    const float* W1f  = (const float*)d_in[bi + 1];
    const float* W1r  = (const float*)d_in[bi + 2];
    const float* b1   = (const float*)d_in[bi + 3];
    const float* g1   = (const float*)d_in[bi + 4];
    const float* be1  = (const float*)d_in[bi + 5];
    const float* m1   = (const float*)d_in[bi + 6];
    const float* v1   = (const float*)d_in[bi + 7];
    const float* W2   = (const float*)d_in[bi + 8];
    const float* b2   = (const float*)d_in[bi + 9];
    const float* g2   = (const float*)d_in[bi + 10];
    const float* be2  = (const float*)d_in[bi + 11];
    const float* m2   = (const float*)d_in[bi + 12];
    const float* v2   = (const float*)d_in[bi + 13];
    const float* lw1  = (const float*)d_in[bi + 14];
    const float* lb1  = (const float*)d_in[bi + 15];
    const float* lw2  = (const float*)d_in[bi + 16];
    const float* lb2  = (const float*)d_in[bi + 17];

    int N = in_sizes[0];
    int E = in_sizes[1] / 2;
    int G = out_size / 3;
    if (N > MAXN) N = MAXN;
    if (E > MAXE) E = MAXE;
    if (G > MAXG) G = MAXG;

    __nv_bfloat162 *hh0, *hh1;
    float *z, *pooled;
    int *deg, *off, *pos, *csr, *bsum;
    cudaGetSymbolAddress((void**)&hh0, g_hh);
    hh1 = hh0 + (size_t)MAXN * 32;
    cudaGetSymbolAddress((void**)&z, g_z);
    cudaGetSymbolAddress((void**)&pooled, g_pooled);
    cudaGetSymbolAddress((void**)&deg, g_deg);
    cudaGetSymbolAddress((void**)&off, g_off);
    cudaGetSymbolAddress((void**)&pos, g_pos);
    cudaGetSymbolAddress((void**)&csr, g_csr);
    cudaGetSymbolAddress((void**)&bsum, g_bsum);

    cudaFuncSetAttribute(gin_node, cudaFuncAttributeMaxDynamicSharedMemorySize,
                         NODE_SMEM_FLOATS * 4);
    cudaFuncSetAttribute(gin_node0, cudaFuncAttributeMaxDynamicSharedMemorySize,
                         NODE0_SMEM_FLOATS * 4);

    int nodeGrid = (N + 127) / 128;
    int edgeGrid = (E + 255) / 256;
    int nScan = N + 1;
    int nb = (nScan + 511) / 512;

    // ----- CSR build -----
    cudaMemsetAsync(deg, 0, (size_t)nScan * sizeof(int));
    cudaMemsetAsync(pooled, 0, (size_t)G * 512 * sizeof(float));
    deg_count<<<edgeGrid, 256>>>(ei, E, deg);
    chunk_sum<<<nb, 512>>>(deg, nScan, bsum);
    scan_bsum<<<1, 1024>>>(bsum, nb);
    chunk_scan<<<nb, 512>>>(deg, nScan, bsum, off, pos);
    csr_scatter<<<edgeGrid, 256>>>(ei, E, pos, csr);

    // ----- layer 0 (scalar input): agg into z (reuse as scalar buffer) -----
    csr_agg1<<<(N + 255) / 256, 256>>>(off, csr, x, z, N);
    gin_node0<<<nodeGrid, 128, NODE0_SMEM_FLOATS * 4>>>(
        x, z, hh0, batch, pooled, eps, W1f,
        b1, g1, be1, m1, v1,
        W2, b2, g2, be2, m2, v2, N);

    // ----- layers 1..7: bf16 gather -> fp32 z -> node MLP -> bf16 hout -----
    for (int i = 1; i < LL; ++i) {
        const __nv_bfloat162* hprev = (i & 1) ? hh0 : hh1;
        __nv_bfloat162* hout = (i & 1) ? hh1 : hh0;
        csr_agg_h<<<((size_t)N * 8 + 255) / 256, 256>>>(off, csr, hprev, z, eps + i, N);
        gin_node<<<nodeGrid, 128, NODE_SMEM_FLOATS * 4>>>(
            z, hout, batch, pooled, i,
            W1r + (size_t)(i - 1) * 4096, b1 + i * 64,
            g1 + i * 64, be1 + i * 64, m1 + i * 64, v1 + i * 64,
            W2 + (size_t)i * 4096, b2 + i * 64,
            g2 + i * 64, be2 + i * 64, m2 + i * 64, v2 + i * 64, N);
    }

    // ----- head -----
    classify_kernel<<<G, 64>>>(pooled, batch, N, lw1, lb1, lw2, lb2, (float*)d_out);
}

// round 6
// speedup vs baseline: 1.5496x; 1.0232x over previous
#include <cuda_runtime.h>
#include <cuda_bf16.h>
#include <math.h>

#define MAXN 100000
#define MAXE 1600000
#define MAXG 500
#define LL 8
#define BN_EPS 1e-5f

// ---------------- device scratch ----------------
__device__ __nv_bfloat162 g_hh[2][(size_t)MAXN * 32];  // bf16 node features (128B rows)
__device__ float g_z[(size_t)MAXN * 64];                // z = (1+eps)*h + agg (fp32)
__device__ float g_pooled[(size_t)MAXG * LL * 64];
__device__ int g_deg[MAXN + 1];
__device__ int g_off[MAXN + 2];
__device__ int g_pos[MAXN + 1];
__device__ int g_csr[MAXE];
__device__ int g_bsum[1024];

// ---------------- f32x2 helpers ----------------
__device__ __forceinline__ unsigned long long pack2(float a, float b) {
    unsigned long long r;
    asm("mov.b64 %0, {%1, %2};" : "=l"(r) : "f"(a), "f"(b));
    return r;
}
__device__ __forceinline__ void unpack2(unsigned long long v, float& a, float& b) {
    asm("mov.b64 {%0, %1}, %2;" : "=f"(a), "=f"(b) : "l"(v));
}
__device__ __forceinline__ void fma2(unsigned long long& acc, unsigned long long a, unsigned long long b) {
    asm("fma.rn.f32x2 %0, %1, %2, %0;" : "+l"(acc) : "l"(a), "l"(b));
}
__device__ __forceinline__ void red4(float4* p, float4 v) {
    asm volatile("red.global.add.v4.f32 [%0], {%1, %2, %3, %4};"
                 :: "l"(p), "f"(v.x), "f"(v.y), "f"(v.z), "f"(v.w) : "memory");
}

// ============ CSR build ============
__global__ __launch_bounds__(256) void deg_count(const int* __restrict__ ei, int E, int* __restrict__ deg) {
    int e = blockIdx.x * 256 + threadIdx.x;
    if (e >= E) return;
    atomicAdd(&deg[ei[E + e]], 1);
}

__global__ __launch_bounds__(512) void chunk_sum(const int* __restrict__ deg, int n, int* __restrict__ bsum) {
    __shared__ int sh[512];
    int t = threadIdx.x;
    int i = blockIdx.x * 512 + t;
    sh[t] = (i < n) ? deg[i] : 0;
    __syncthreads();
#pragma unroll
    for (int s = 256; s > 0; s >>= 1) {
        if (t < s) sh[t] += sh[t + s];
        __syncthreads();
    }
    if (t == 0) bsum[blockIdx.x] = sh[0];
}

__global__ __launch_bounds__(1024) void scan_bsum(int* __restrict__ bsum, int nb) {
    __shared__ int sh[1024];
    int t = threadIdx.x;
    int v = (t < nb) ? bsum[t] : 0;
    sh[t] = v;
    __syncthreads();
    for (int d = 1; d < 1024; d <<= 1) {
        int add = (t >= d) ? sh[t - d] : 0;
        __syncthreads();
        sh[t] += add;
        __syncthreads();
    }
    if (t < nb) bsum[t] = sh[t] - v;   // exclusive
}

__global__ __launch_bounds__(512) void chunk_scan(const int* __restrict__ deg, int n,
                                                  const int* __restrict__ bsum,
                                                  int* __restrict__ off, int* __restrict__ pos) {
    __shared__ int sh[512];
    int t = threadIdx.x;
    int i = blockIdx.x * 512 + t;
    int v = (i < n) ? deg[i] : 0;
    sh[t] = v;
    __syncthreads();
    for (int d = 1; d < 512; d <<= 1) {
        int add = (t >= d) ? sh[t - d] : 0;
        __syncthreads();
        sh[t] += add;
        __syncthreads();
    }
    if (i < n) {
        int ex = sh[t] - v + bsum[blockIdx.x];
        off[i] = ex;
        pos[i] = ex;
    }
}

__global__ __launch_bounds__(256) void csr_scatter(const int* __restrict__ ei, int E,
                                                   int* __restrict__ pos, int* __restrict__ csr) {
    int e = blockIdx.x * 256 + threadIdx.x;
    if (e >= E) return;
    int src = ei[e];
    int dst = ei[E + e];
    int p = atomicAdd(&pos[dst], 1);
    csr[p] = src;
}

// ============ CSR aggregation (bf16 rows -> fp32 z) ============
__device__ __forceinline__ void addrow(float4 v, float* acc) {
    const __nv_bfloat162* h = reinterpret_cast<const __nv_bfloat162*>(&v);
#pragma unroll
    for (int j = 0; j < 4; ++j) {
        float2 f = __bfloat1622float2(h[j]);
        acc[2 * j]     += f.x;
        acc[2 * j + 1] += f.y;
    }
}

// 8 threads per node, each thread covers 8 contiguous features (16B).
__global__ __launch_bounds__(256) void csr_agg_h(const int* __restrict__ off, const int* __restrict__ csr,
                                                 const __nv_bfloat162* __restrict__ hh, float* __restrict__ z,
                                                 const float* __restrict__ eps, int N) {
    int t = blockIdx.x * 256 + threadIdx.x;
    int n = t >> 3;
    if (n >= N) return;
    int q = t & 7;
    const float4* hq = reinterpret_cast<const float4*>(hh) + q;
    float acc[8];
#pragma unroll
    for (int j = 0; j < 8; ++j) acc[j] = 0.f;
    int b = off[n], e = off[n + 1];
    int i = b;
    for (; i + 8 <= e; i += 8) {
        int idx[8];
#pragma unroll
        for (int u = 0; u < 8; ++u) idx[u] = __ldg(&csr[i + u]);
        float4 v[8];
#pragma unroll
        for (int u = 0; u < 8; ++u) v[u] = hq[idx[u] * 8];
#pragma unroll
        for (int u = 0; u < 8; ++u) addrow(v[u], acc);
    }
    for (; i + 4 <= e; i += 4) {
        int i0 = __ldg(&csr[i]);
        int i1 = __ldg(&csr[i + 1]);
        int i2 = __ldg(&csr[i + 2]);
        int i3 = __ldg(&csr[i + 3]);
        float4 v0 = hq[i0 * 8];
        float4 v1 = hq[i1 * 8];
        float4 v2 = hq[i2 * 8];
        float4 v3 = hq[i3 * 8];
        addrow(v0, acc);
        addrow(v1, acc);
        addrow(v2, acc);
        addrow(v3, acc);
    }
    for (; i < e; ++i) addrow(hq[__ldg(&csr[i]) * 8], acc);

    // self term
    float ev = 1.0f + eps[0];
    float4 sv = hq[n * 8];
    const __nv_bfloat162* sh2 = reinterpret_cast<const __nv_bfloat162*>(&sv);
    float4 o0, o1;
    {
        float2 f0 = __bfloat1622float2(sh2[0]);
        float2 f1 = __bfloat1622float2(sh2[1]);
        float2 f2 = __bfloat1622float2(sh2[2]);
        float2 f3 = __bfloat1622float2(sh2[3]);
        o0.x = fmaf(ev, f0.x, acc[0]);
        o0.y = fmaf(ev, f0.y, acc[1]);
        o0.z = fmaf(ev, f1.x, acc[2]);
        o0.w = fmaf(ev, f1.y, acc[3]);
        o1.x = fmaf(ev, f2.x, acc[4]);
        o1.y = fmaf(ev, f2.y, acc[5]);
        o1.z = fmaf(ev, f3.x, acc[6]);
        o1.w = fmaf(ev, f3.y, acc[7]);
    }
    float4* zp = reinterpret_cast<float4*>(z + (size_t)n * 64 + q * 8);
    zp[0] = o0;
    zp[1] = o1;
}

// scalar features (layer 0)
__global__ __launch_bounds__(256) void csr_agg1(const int* __restrict__ off, const int* __restrict__ csr,
                                                const float* __restrict__ x, float* __restrict__ agg, int N) {
    int n = blockIdx.x * 256 + threadIdx.x;
    if (n >= N) return;
    int b = off[n], e = off[n + 1];
    float s = 0.f;
    int i = b;
    for (; i + 4 <= e; i += 4) {
        float v0 = x[__ldg(&csr[i])];
        float v1 = x[__ldg(&csr[i + 1])];
        float v2 = x[__ldg(&csr[i + 2])];
        float v3 = x[__ldg(&csr[i + 3])];
        s += (v0 + v1) + (v2 + v3);
    }
    for (; i < e; ++i) s += x[__ldg(&csr[i])];
    agg[n] = s;
}

// ============ node MLP (register-tiled 8x8 GEMM) ============
#define NODE_SMEM_FLOATS (4096 + 4096 + 384 + 128 * 65)
#define NODE0_SMEM_FLOATS (4096 + 384 + 64 + 128 * 65)

__device__ __forceinline__ void load_bn_params(float* prm, int tid,
        const float* b1, const float* g1, const float* be1, const float* m1, const float* v1,
        const float* b2, const float* g2, const float* be2, const float* m2, const float* v2) {
    if (tid < 64) {
        float s1 = g1[tid] * rsqrtf(v1[tid] + BN_EPS);
        prm[tid]       = b1[tid];
        prm[64 + tid]  = s1;
        prm[128 + tid] = fmaf(-m1[tid], s1, be1[tid]);
        float s2 = g2[tid] * rsqrtf(v2[tid] + BN_EPS);
        prm[192 + tid] = b2[tid];
        prm[256 + tid] = s2;
        prm[320 + tid] = fmaf(-m2[tid], s2, be2[tid]);
    }
}

__device__ __forceinline__ void gemm_tile(const float* __restrict__ Wsh,
                                          const float* __restrict__ zs,
                                          int r, int c, unsigned long long acc[8][4]) {
    const float* zbase = zs + r * 8 * 65;
    const float* wbase = Wsh + c * 8;
#pragma unroll 2
    for (int k = 0; k < 64; ++k) {
        unsigned long long zz[8];
#pragma unroll
        for (int i = 0; i < 8; ++i) {
            float z = zbase[i * 65 + k];
            zz[i] = pack2(z, z);
        }
        ulonglong2 wa = *reinterpret_cast<const ulonglong2*>(wbase + k * 64);
        ulonglong2 wb = *reinterpret_cast<const ulonglong2*>(wbase + k * 64 + 4);
#pragma unroll
        for (int i = 0; i < 8; ++i) {
            fma2(acc[i][0], zz[i], wa.x);
            fma2(acc[i][1], zz[i], wa.y);
            fma2(acc[i][2], zz[i], wb.x);
            fma2(acc[i][3], zz[i], wb.y);
        }
    }
}

// BN2 + write bf16 hout + RED pooled.
// batch is sorted, so the 8 contiguous nodes of this thread usually share one
// graph id: pre-reduce the pooled contribution in registers and emit 2 red4
// instead of 16 on that path (fp32 pre-association, same segment-sum semantics).
__device__ __forceinline__ void epilogue(unsigned long long acc[8][4], const float* prm, int c,
                                         int n0, int r, int N, const int* sh_b,
                                         __nv_bfloat162* houth, float* pooled, int layer) {
    float4 b2a = *reinterpret_cast<const float4*>(prm + 192 + c * 8);
    float4 b2b = *reinterpret_cast<const float4*>(prm + 192 + c * 8 + 4);
    float4 s2a = *reinterpret_cast<const float4*>(prm + 256 + c * 8);
    float4 s2b = *reinterpret_cast<const float4*>(prm + 256 + c * 8 + 4);
    float4 t2a = *reinterpret_cast<const float4*>(prm + 320 + c * 8);
    float4 t2b = *reinterpret_cast<const float4*>(prm + 320 + c * 8 + 4);

    int base = r * 8;
    int g0 = sh_b[base];
    bool uni = (n0 + base + 7 < N);
    if (uni) {
#pragma unroll
        for (int i = 1; i < 8; ++i) uni = uni && (sh_b[base + i] == g0);
    }
    float4 sa = make_float4(0.f, 0.f, 0.f, 0.f);
    float4 sb = make_float4(0.f, 0.f, 0.f, 0.f);

#pragma unroll
    for (int i = 0; i < 8; ++i) {
        int node = base + i;
        int n = n0 + node;
        if (n >= N) break;
        float f0, f1, f2, f3, f4, f5, f6, f7;
        unpack2(acc[i][0], f0, f1);
        unpack2(acc[i][1], f2, f3);
        unpack2(acc[i][2], f4, f5);
        unpack2(acc[i][3], f6, f7);
        float4 oa, ob;
        oa.x = fmaf(fmaxf(f0 + b2a.x, 0.f), s2a.x, t2a.x);
        oa.y = fmaf(fmaxf(f1 + b2a.y, 0.f), s2a.y, t2a.y);
        oa.z = fmaf(fmaxf(f2 + b2a.z, 0.f), s2a.z, t2a.z);
        oa.w = fmaf(fmaxf(f3 + b2a.w, 0.f), s2a.w, t2a.w);
        ob.x = fmaf(fmaxf(f4 + b2b.x, 0.f), s2b.x, t2b.x);
        ob.y = fmaf(fmaxf(f5 + b2b.y, 0.f), s2b.y, t2b.y);
        ob.z = fmaf(fmaxf(f6 + b2b.z, 0.f), s2b.z, t2b.z);
        ob.w = fmaf(fmaxf(f7 + b2b.w, 0.f), s2b.w, t2b.w);
        __nv_bfloat162 p0 = __floats2bfloat162_rn(oa.x, oa.y);
        __nv_bfloat162 p1 = __floats2bfloat162_rn(oa.z, oa.w);
        __nv_bfloat162 p2 = __floats2bfloat162_rn(ob.x, ob.y);
        __nv_bfloat162 p3 = __floats2bfloat162_rn(ob.z, ob.w);
        uint4 u;
        u.x = *reinterpret_cast<unsigned*>(&p0);
        u.y = *reinterpret_cast<unsigned*>(&p1);
        u.z = *reinterpret_cast<unsigned*>(&p2);
        u.w = *reinterpret_cast<unsigned*>(&p3);
        reinterpret_cast<uint4*>(houth)[n * 8 + c] = u;
        if (uni) {
            sa.x += oa.x; sa.y += oa.y; sa.z += oa.z; sa.w += oa.w;
            sb.x += ob.x; sb.y += ob.y; sb.z += ob.z; sb.w += ob.w;
        } else {
            int g = sh_b[node];
            float4* pp = reinterpret_cast<float4*>(pooled) + (size_t)g * 128 + layer * 16 + c * 2;
            red4(pp, oa);
            red4(pp + 1, ob);
        }
    }
    if (uni) {
        float4* pp = reinterpret_cast<float4*>(pooled) + (size_t)g0 * 128 + layer * 16 + c * 2;
        red4(pp, sa);
        red4(pp + 1, sb);
    }
}

__device__ __forceinline__ void mid_bn_store(unsigned long long acc[8][4], const float* prm, int c,
                                             int r, float* zs) {
    float4 b1a = *reinterpret_cast<const float4*>(prm + c * 8);
    float4 b1b = *reinterpret_cast<const float4*>(prm + c * 8 + 4);
    float4 s1a = *reinterpret_cast<const float4*>(prm + 64 + c * 8);
    float4 s1b = *reinterpret_cast<const float4*>(prm + 64 + c * 8 + 4);
    float4 t1a = *reinterpret_cast<const float4*>(prm + 128 + c * 8);
    float4 t1b = *reinterpret_cast<const float4*>(prm + 128 + c * 8 + 4);
#pragma unroll
    for (int i = 0; i < 8; ++i) {
        float* zr = zs + (r * 8 + i) * 65 + c * 8;
        float f0, f1, f2, f3, f4, f5, f6, f7;
        unpack2(acc[i][0], f0, f1);
        unpack2(acc[i][1], f2, f3);
        unpack2(acc[i][2], f4, f5);
        unpack2(acc[i][3], f6, f7);
        zr[0] = fmaf(fmaxf(f0 + b1a.x, 0.f), s1a.x, t1a.x);
        zr[1] = fmaf(fmaxf(f1 + b1a.y, 0.f), s1a.y, t1a.y);
        zr[2] = fmaf(fmaxf(f2 + b1a.z, 0.f), s1a.z, t1a.z);
        zr[3] = fmaf(fmaxf(f3 + b1a.w, 0.f), s1a.w, t1a.w);
        zr[4] = fmaf(fmaxf(f4 + b1b.x, 0.f), s1b.x, t1b.x);
        zr[5] = fmaf(fmaxf(f5 + b1b.y, 0.f), s1b.y, t1b.y);
        zr[6] = fmaf(fmaxf(f6 + b1b.z, 0.f), s1b.z, t1b.z);
        zr[7] = fmaf(fmaxf(f7 + b1b.w, 0.f), s1b.w, t1b.w);
    }
}

__global__ __launch_bounds__(128) void gin_node(
        const float* __restrict__ zsrc,
        __nv_bfloat162* __restrict__ houth, const int* __restrict__ batch,
        float* __restrict__ pooled, int layer,
        const float* __restrict__ W1, const float* __restrict__ b1,
        const float* __restrict__ g1, const float* __restrict__ be1,
        const float* __restrict__ m1, const float* __restrict__ v1,
        const float* __restrict__ W2, const float* __restrict__ b2,
        const float* __restrict__ g2, const float* __restrict__ be2,
        const float* __restrict__ m2, const float* __restrict__ v2, int N) {
    extern __shared__ float sm[];
    float* W1s = sm;
    float* W2s = sm + 4096;
    float* prm = sm + 8192;
    float* zs  = sm + 8576;
    __shared__ int sh_b[128];
    int tid = threadIdx.x;

    float4* w1d = reinterpret_cast<float4*>(W1s);
    float4* w2d = reinterpret_cast<float4*>(W2s);
    const float4* w1g = reinterpret_cast<const float4*>(W1);
    const float4* w2g = reinterpret_cast<const float4*>(W2);
#pragma unroll
    for (int i = tid; i < 1024; i += 128) { w1d[i] = w1g[i]; w2d[i] = w2g[i]; }
    load_bn_params(prm, tid, b1, g1, be1, m1, v1, b2, g2, be2, m2, v2);

    int n0 = blockIdx.x * 128;
    int n = n0 + tid;
    float* zr = zs + tid * 65;
    if (n < N) {
        sh_b[tid] = batch[n];
        const float4* zp = reinterpret_cast<const float4*>(zsrc) + n * 16;
#pragma unroll
        for (int q = 0; q < 16; ++q) {
            float4 v = zp[q];
            zr[4 * q + 0] = v.x;
            zr[4 * q + 1] = v.y;
            zr[4 * q + 2] = v.z;
            zr[4 * q + 3] = v.w;
        }
    } else {
        sh_b[tid] = 0;
#pragma unroll
        for (int q = 0; q < 64; ++q) zr[q] = 0.f;
    }
    __syncthreads();

    int r = tid >> 3, c = tid & 7;
    unsigned long long acc[8][4];
#pragma unroll
    for (int i = 0; i < 8; ++i)
#pragma unroll
        for (int p = 0; p < 4; ++p) acc[i][p] = 0ull;

    gemm_tile(W1s, zs, r, c, acc);
    __syncthreads();
    mid_bn_store(acc, prm, c, r, zs);
#pragma unroll
    for (int i = 0; i < 8; ++i)
#pragma unroll
        for (int p = 0; p < 4; ++p) acc[i][p] = 0ull;
    __syncthreads();
    gemm_tile(W2s, zs, r, c, acc);
    epilogue(acc, prm, c, n0, r, N, sh_b, houth, pooled, layer);
}

__global__ __launch_bounds__(128) void gin_node0(
        const float* __restrict__ x, const float* __restrict__ agg,
        __nv_bfloat162* __restrict__ houth, const int* __restrict__ batch,
        float* __restrict__ pooled, const float* __restrict__ eps,
        const float* __restrict__ W1f, const float* __restrict__ b1,
        const float* __restrict__ g1, const float* __restrict__ be1,
        const float* __restrict__ m1, const float* __restrict__ v1,
        const float* __restrict__ W2, const float* __restrict__ b2,
        const float* __restrict__ g2, const float* __restrict__ be2,
        const float* __restrict__ m2, const float* __restrict__ v2, int N) {
    extern __shared__ float sm[];
    float* W2s = sm;
    float* prm = sm + 4096;
    float* w1f = sm + 4480;
    float* zs  = sm + 4544;
    __shared__ int sh_b[128];
    int tid = threadIdx.x;

    float4* w2d = reinterpret_cast<float4*>(W2s);
    const float4* w2g = reinterpret_cast<const float4*>(W2);
#pragma unroll
    for (int i = tid; i < 1024; i += 128) w2d[i] = w2g[i];
    if (tid < 64) w1f[tid] = W1f[tid];
    load_bn_params(prm, tid, b1, g1, be1, m1, v1, b2, g2, be2, m2, v2);
    __syncthreads();

    int n0 = blockIdx.x * 128;
    int n = n0 + tid;
    float* zrow = zs + tid * 65;
    if (n < N) {
        sh_b[tid] = batch[n];
        float ev = 1.0f + eps[0];
        float z = fmaf(ev, x[n], agg[n]);
#pragma unroll
        for (int j = 0; j < 64; ++j) {
            float y = fmaxf(fmaf(z, w1f[j], prm[j]), 0.f);
            zrow[j] = fmaf(y, prm[64 + j], prm[128 + j]);
        }
    } else {
        sh_b[tid] = 0;
#pragma unroll
        for (int j = 0; j < 64; ++j) zrow[j] = 0.f;
    }
    __syncthreads();

    int r = tid >> 3, c = tid & 7;
    unsigned long long acc[8][4];
#pragma unroll
    for (int i = 0; i < 8; ++i)
#pragma unroll
        for (int p = 0; p < 4; ++p) acc[i][p] = 0ull;
    gemm_tile(W2s, zs, r, c, acc);
    epilogue(acc, prm, c, n0, r, N, sh_b, houth, pooled, 0);
}

// ---------------- classifier head ----------------
__device__ __forceinline__ int lbound(const int* __restrict__ a, int n, int v) {
    int lo = 0, hi = n;
    while (lo < hi) {
        int mid = (lo + hi) >> 1;
        if (a[mid] < v) lo = mid + 1; else hi = mid;
    }
    return lo;
}

__global__ __launch_bounds__(64) void classify_kernel(
        const float* __restrict__ pooled, const int* __restrict__ batch, int N,
        const float* __restrict__ lw1, const float* __restrict__ lb1,
        const float* __restrict__ lw2, const float* __restrict__ lb2,
        float* __restrict__ out) {
    __shared__ float ps[512];
    __shared__ float hid[64];
    __shared__ float lg[3];
    __shared__ float inv;
    int g = blockIdx.x;
    int tid = threadIdx.x;
    if (tid == 0) {
        int a = lbound(batch, N, g);
        int b = lbound(batch, N, g + 1);
        int c = b - a;
        inv = 1.0f / (float)(c > 1 ? c : 1);
    }
    __syncthreads();
    for (int k = tid; k < 512; k += 64) ps[k] = pooled[(size_t)g * 512 + k] * inv;
    __syncthreads();
    float acc = lb1[tid];
#pragma unroll 8
    for (int k = 0; k < 512; ++k) acc = fmaf(ps[k], lw1[k * 64 + tid], acc);
    hid[tid] = fmaxf(acc, 0.f);
    __syncthreads();
    if (tid < 3) {
        float s = lb2[tid];
#pragma unroll
        for (int j = 0; j < 64; ++j) s = fmaf(hid[j], lw2[j * 3 + tid], s);
        lg[tid] = s;
    }
    __syncthreads();
    if (tid == 0) {
        float m = fmaxf(lg[0], fmaxf(lg[1], lg[2]));
        float e = expf(lg[0] - m) + expf(lg[1] - m) + expf(lg[2] - m);
        float lse = m + logf(e);
        out[g * 3 + 0] = lg[0] - lse;
        out[g * 3 + 1] = lg[1] - lse;
        out[g * 3 + 2] = lg[2] - lse;
    }
}

// ---------------- launcher ----------------
extern "C" void kernel_launch(void* const* d_in, const int* in_sizes, int n_in,
                              void* d_out, int out_size) {
    const float* x     = (const float*)d_in[0];
    const int*   ei    = (const int*)d_in[1];
    const int*   batch = (const int*)d_in[2];
    int bi = (in_sizes[3] == 1) ? 4 : 3;
    const float* eps  = (const float*)d_in[bi + 0];
    const float* W1f  = (const float*)d_in[bi + 1];
    const float* W1r  = (const float*)d_in[bi + 2];
    const float* b1   = (const float*)d_in[bi + 3];
    const float* g1   = (const float*)d_in[bi + 4];
    const float* be1  = (const float*)d_in[bi + 5];
    const float* m1   = (const float*)d_in[bi + 6];
    const float* v1   = (const float*)d_in[bi + 7];
    const float* W2   = (const float*)d_in[bi + 8];
    const float* b2   = (const float*)d_in[bi + 9];
    const float* g2   = (const float*)d_in[bi + 10];
    const float* be2  = (const float*)d_in[bi + 11];
    const float* m2   = (const float*)d_in[bi + 12];
    const float* v2   = (const float*)d_in[bi + 13];
    const float* lw1  = (const float*)d_in[bi + 14];
    const float* lb1  = (const float*)d_in[bi + 15];
    const float* lw2  = (const float*)d_in[bi + 16];
    const float* lb2  = (const float*)d_in[bi + 17];

    int N = in_sizes[0];
    int E = in_sizes[1] / 2;
    int G = out_size / 3;
    if (N > MAXN) N = MAXN;
    if (E > MAXE) E = MAXE;
    if (G > MAXG) G = MAXG;

    __nv_bfloat162 *hh0, *hh1;
    float *z, *pooled;
    int *deg, *off, *pos, *csr, *bsum;
    cudaGetSymbolAddress((void**)&hh0, g_hh);
    hh1 = hh0 + (size_t)MAXN * 32;
    cudaGetSymbolAddress((void**)&z, g_z);
    cudaGetSymbolAddress((void**)&pooled, g_pooled);
    cudaGetSymbolAddress((void**)&deg, g_deg);
    cudaGetSymbolAddress((void**)&off, g_off);
    cudaGetSymbolAddress((void**)&pos, g_pos);
    cudaGetSymbolAddress((void**)&csr, g_csr);
    cudaGetSymbolAddress((void**)&bsum, g_bsum);

    cudaFuncSetAttribute(gin_node, cudaFuncAttributeMaxDynamicSharedMemorySize,
                         NODE_SMEM_FLOATS * 4);
    cudaFuncSetAttribute(gin_node0, cudaFuncAttributeMaxDynamicSharedMemorySize,
                         NODE0_SMEM_FLOATS * 4);

    int nodeGrid = (N + 127) / 128;
    int edgeGrid = (E + 255) / 256;
    int nScan = N + 1;
    int nb = (nScan + 511) / 512;

    // ----- CSR build -----
    cudaMemsetAsync(deg, 0, (size_t)nScan * sizeof(int));
    cudaMemsetAsync(pooled, 0, (size_t)G * 512 * sizeof(float));
    deg_count<<<edgeGrid, 256>>>(ei, E, deg);
    chunk_sum<<<nb, 512>>>(deg, nScan, bsum);
    scan_bsum<<<1, 1024>>>(bsum, nb);
    chunk_scan<<<nb, 512>>>(deg, nScan, bsum, off, pos);
    csr_scatter<<<edgeGrid, 256>>>(ei, E, pos, csr);

    // ----- layer 0 (scalar input): agg into z (reuse as scalar buffer) -----
    csr_agg1<<<(N + 255) / 256, 256>>>(off, csr, x, z, N);
    gin_node0<<<nodeGrid, 128, NODE0_SMEM_FLOATS * 4>>>(
        x, z, hh0, batch, pooled, eps, W1f,
        b1, g1, be1, m1, v1,
        W2, b2, g2, be2, m2, v2, N);

    // ----- layers 1..7: bf16 gather -> fp32 z -> node MLP -> bf16 hout -----
    for (int i = 1; i < LL; ++i) {
        const __nv_bfloat162* hprev = (i & 1) ? hh0 : hh1;
        __nv_bfloat162* hout = (i & 1) ? hh1 : hh0;
        csr_agg_h<<<((size_t)N * 8 + 255) / 256, 256>>>(off, csr, hprev, z, eps + i, N);
        gin_node<<<nodeGrid, 128, NODE_SMEM_FLOATS * 4>>>(
            z, hout, batch, pooled, i,
            W1r + (size_t)(i - 1) * 4096, b1 + i * 64,
            g1 + i * 64, be1 + i * 64, m1 + i * 64, v1 + i * 64,
            W2 + (size_t)i * 4096, b2 + i * 64,
            g2 + i * 64, be2 + i * 64, m2 + i * 64, v2 + i * 64, N);
    }

    // ----- head -----
    classify_kernel<<<G, 64>>>(pooled, batch, N, lw1, lb1, lw2, lb2, (float*)d_out);
}